// round 8
// baseline (speedup 1.0000x reference)
#include <cuda_runtime.h>

#define NB    32
#define NC    2
#define PP    262144             // H*W
#define BINS  2048
#define ROWS  (NC * NB)          // 64 rows, row = cc*NB + n
#define BPS   8                  // blocks per sample -> 256 blocks
#define HT    1024               // threads per block
#define NW    (HT / 32)
#define PXB   (PP / BPS)         // 32768 pixels per block
#define ITERS (PXB / (HT * 4))   // 8 iterations of 4 pixels
#define SEG   (BINS / HT)        // 2 bins per thread in the tail scan

// Scratch (static device globals, zero-initialized at load; reset each call)
__device__ unsigned int g_part[(size_t)NB * BPS * NC * BINS]; // per-block partial hists (overwritten)
__device__ int          g_npred[ROWS];
__device__ int          g_cnt[NB];            // per-sample arrival counters
__device__ int          g_done;               // sample-completion counter
__device__ float        g_wrow[ROWS];
__device__ unsigned int g_valid[ROWS];

__global__ void __launch_bounds__(HT) k_all(const float* __restrict__ x,
                                            const void*  __restrict__ tgt,
                                            const float* __restrict__ cw,
                                            const float* __restrict__ tw,
                                            float* __restrict__ out) {
  __shared__ unsigned int       sh[2 * BINS];   // 16 KB hist
  __shared__ unsigned long long swarp[NW];
  __shared__ float              sred[NW];
  __shared__ int                s0[NW], s1[NW];
  __shared__ int                sflag, slast;

  const int n    = blockIdx.y;
  const int b    = blockIdx.x;
  const int tid  = threadIdx.x;
  const int lane = tid & 31;
  const int w    = tid >> 5;

  for (int i = tid; i < 2 * BINS; i += HT) sh[i] = 0u;

  // Detect targets dtype: if int32, odd 32-bit words carry real data -> some
  // nonzero. If int64 (values 0/1), odd words are all zero. Doubles as barrier.
  const int* t32 = (const int*)tgt;
  int probe = t32[2 * tid + 1];
  bool is32 = __syncthreads_or(probe != 0);

  // ---------------- histogram phase ----------------
  const int base = b * PXB;
  int c0 = 0, c1 = 0;
#pragma unroll 4
  for (int it = 0; it < ITERS; it++) {
    const int p = base + (it * HT + tid) * 4;

    long long tv[4];
    if (is32) {
      int4 q = *(const int4*)(t32 + (size_t)n * PP + p);
      tv[0] = q.x; tv[1] = q.y; tv[2] = q.z; tv[3] = q.w;
    } else {
      longlong4 q = *(const longlong4*)((const long long*)tgt + (size_t)n * PP + p);
      tv[0] = q.x; tv[1] = q.y; tv[2] = q.z; tv[3] = q.w;
    }
    float4 v0 = *(const float4*)(x + ((size_t)n * NC + 0) * PP + p);
    float4 v1 = *(const float4*)(x + ((size_t)n * NC + 1) * PP + p);
    float xs0[4] = {v0.x, v0.y, v0.z, v0.w};
    float xs1[4] = {v1.x, v1.y, v1.z, v1.w};

#pragma unroll
    for (int k = 0; k < 4; k++) {
      bool  m0 = (tv[k] == 0);            // class-0 mask; class-1 mask = !m0
      float a0 = xs0[k], a1 = xs1[k];
      c0 += (a0 > 0.25f);
      c1 += (a1 > 0.25f);
      float d0 = m0 ? (1.0f - a0) : a0;   // |mask - x|
      float d1 = m0 ? a1 : (1.0f - a1);
      unsigned int b0 = min((unsigned int)(d0 * (float)BINS), (unsigned int)(BINS - 1));
      unsigned int b1 = min((unsigned int)(d1 * (float)BINS), (unsigned int)(BINS - 1));
      atomicAdd(&sh[b0],        m0 ? 0x10000u : 1u);
      atomicAdd(&sh[BINS + b1], m0 ? 1u : 0x10000u);
    }
  }
  __syncthreads();

  // flush: plain vectorized stores to this block's private slot
  uint4* __restrict__ dst =
      (uint4*)(g_part + ((size_t)(n * BPS + b) * NC) * BINS);
  const uint4* __restrict__ src = (const uint4*)sh;
#pragma unroll
  for (int i = tid; i < (2 * BINS) / 4; i += HT) dst[i] = src[i];

  // npred block reduce + 2 global atomics
#pragma unroll
  for (int off = 16; off; off >>= 1) {
    c0 += __shfl_down_sync(0xffffffffu, c0, off);
    c1 += __shfl_down_sync(0xffffffffu, c1, off);
  }
  if (lane == 0) { s0[w] = c0; s1[w] = c1; }
  __syncthreads();
  if (tid == 0) {
    int a = 0, bb = 0;
#pragma unroll
    for (int i = 0; i < NW; i++) { a += s0[i]; bb += s1[i]; }
    atomicAdd(&g_npred[n], a);
    atomicAdd(&g_npred[NB + n], bb);
  }

  // ---------------- arrival: last block of this sample runs the scan tail ----
  __threadfence();              // flush stores + npred atomics globally visible
  __syncthreads();
  if (tid == 0) {
    int old = atomicAdd(&g_cnt[n], 1);
    sflag = (old == BPS - 1);
  }
  __syncthreads();
  if (!sflag) return;
  __threadfence();              // acquire

  // ---------------- scan tail: both class rows of sample n ----------------
  for (int cc = 0; cc < NC; cc++) {
    const int r = cc * NB + n;
    // thread owns SEG=2 bins [g, g+1]; thread 0 owns the HIGHEST bins
    const int g = BINS - SEG - tid * SEG;

    unsigned int h1[SEG], htot[SEG];
#pragma unroll
    for (int j = 0; j < SEG; j++) { h1[j] = 0u; htot[j] = 0u; }

#pragma unroll
    for (int bb = 0; bb < BPS; bb++) {
      uint2 v = __ldcg((const uint2*)(g_part +
                 ((size_t)(n * BPS + bb) * NC + cc) * BINS + g));
      unsigned int vv[2] = {v.x, v.y};
#pragma unroll
      for (int j = 0; j < SEG; j++) {
        unsigned int one = vv[j] >> 16;
        h1[j]   += one;
        htot[j] += one + (vv[j] & 0xffffu);
      }
    }

    unsigned int ss1 = 0, sst = 0;
#pragma unroll
    for (int j = 0; j < SEG; j++) { ss1 += h1[j]; sst += htot[j]; }

    // inclusive block scan over packed (s1|st)
    unsigned long long mine = ((unsigned long long)ss1 << 32) | (unsigned long long)sst;
    unsigned long long inc = mine;
#pragma unroll
    for (int off = 1; off < 32; off <<= 1) {
      unsigned long long u = __shfl_up_sync(0xffffffffu, inc, off);
      if (lane >= off) inc += u;
    }
    if (lane == 31) swarp[w] = inc;
    __syncthreads();
    if (w == 0) {
      unsigned long long v = (lane < NW) ? swarp[lane] : 0ull;
#pragma unroll
      for (int off = 1; off < NW; off <<= 1) {
        unsigned long long u = __shfl_up_sync(0xffffffffu, v, off);
        if (lane >= off) v += u;
      }
      if (lane < NW) swarp[lane] = v;
    }
    __syncthreads();
    unsigned long long woff = (w == 0) ? 0ull : swarp[w - 1];
    unsigned long long tot  = swarp[NW - 1];
    unsigned long long excl = woff + inc - mine;

    const unsigned int gts = (unsigned int)(tot >> 32);
    unsigned int K1 = (unsigned int)(excl >> 32);
    unsigned int K  = (unsigned int)(excl & 0xffffffffull);

    float iou_prev = (K == 0)
        ? 0.0f
        : 1.0f - __fdividef((float)(gts - K1), (float)(gts + K - K1));

    float acc = 0.0f;
#pragma unroll
    for (int j = SEG - 1; j >= 0; j--) {
      if (htot[j]) {
        K1 += h1[j];
        K  += htot[j];
        float iou = 1.0f - __fdividef((float)(gts - K1), (float)(gts + K - K1));
        float d   = ((float)(g + j) + 0.5f) * (1.0f / (float)BINS);
        acc += d * (iou - iou_prev);
        iou_prev = iou;
      }
    }

    // block reduce acc (fixed tree -> deterministic)
#pragma unroll
    for (int off = 16; off; off >>= 1)
      acc += __shfl_down_sync(0xffffffffu, acc, off);
    if (lane == 0) sred[w] = acc;
    __syncthreads();
    if (tid == 0) {
      float per = 0.0f;
#pragma unroll
      for (int i = 0; i < NW; i++) per += sred[i];
      int   np    = __ldcg(&g_npred[r]);
      float cwv   = cw[cc];
      bool  empty = (gts == 0) && (np == 0);
      bool  valid = (cwv != 0.0f) && !empty;
      g_wrow[r]  = valid ? per * tw[n] * cwv : 0.0f;
      g_valid[r] = valid ? 1u : 0u;
      g_npred[r] = 0;                  // reset for next replay
    }
    __syncthreads();
  }

  // ---------------- completion: last sample-finisher does the final sum ----
  if (tid == 0) {
    g_cnt[n] = 0;                      // reset for next replay
    __threadfence();
    int old = atomicAdd(&g_done, 1);
    slast = (old == NB - 1);
  }
  __syncthreads();
  if (!slast) return;
  __threadfence();

  // parallel deterministic final reduction (64 lanes of warps 0-1)
  {
    float Wv = 0.0f, Vv = 0.0f;
    if (tid < ROWS) {
      Wv = __ldcg(&g_wrow[tid]);
      Vv = (float)__ldcg(&g_valid[tid]);
    }
    if (tid < 64) {
#pragma unroll
      for (int off = 16; off; off >>= 1) {
        Wv += __shfl_down_sync(0xffffffffu, Wv, off);
        Vv += __shfl_down_sync(0xffffffffu, Vv, off);
      }
      if (lane == 0) { sred[w] = Wv; ((float*)swarp)[w] = Vv; }
    }
    __syncthreads();
    if (tid == 0) {
      float W = sred[0] + sred[1];
      float V = ((float*)swarp)[0] + ((float*)swarp)[1];
      out[0] = W / (float)NB / V;
      g_done = 0;                      // reset for next replay
    }
  }
}

// ---------------------------------------------------------------- launch
extern "C" void kernel_launch(void* const* d_in, const int* in_sizes, int n_in,
                              void* d_out, int out_size) {
  const float* x   = (const float*)d_in[0];
  const void*  tgt = d_in[1];
  const float* cw  = (const float*)d_in[2];
  const float* tw  = (const float*)d_in[3];
  float* out = (float*)d_out;

  dim3 grid(BPS, NB);
  k_all<<<grid, HT>>>(x, tgt, cw, tw, out);
}

// round 9
// speedup vs baseline: 1.0696x; 1.0696x over previous
#include <cuda_runtime.h>

#define NB    32
#define NC    2
#define PP    262144             // H*W
#define BINS  2048
#define ROWS  (NC * NB)          // 64 rows, row = cc*NB + n
#define BPS   8                  // blocks per sample -> 256 blocks
#define HT    1024               // threads per block
#define NW    (HT / 32)
#define PXB   (PP / BPS)         // 32768 pixels per block
#define ITERS (PXB / (HT * 4))   // 8 iterations of 4 pixels
#define SEG   (BINS / HT)        // 2 bins per thread in the tail scan

// Scratch (static device globals, zero-initialized at load; reset each call)
__device__ unsigned int g_part[(size_t)NB * BPS * NC * BINS]; // per-block partial hists (overwritten)
__device__ int          g_npred[ROWS];
__device__ int          g_cnt[NB];            // per-sample arrival counters
__device__ int          g_done;               // sample-completion counter
__device__ float        g_wrow[ROWS];
__device__ unsigned int g_valid[ROWS];

__global__ void __launch_bounds__(HT, 2) k_all(const float* __restrict__ x,
                                               const void*  __restrict__ tgt,
                                               const float* __restrict__ cw,
                                               const float* __restrict__ tw,
                                               float* __restrict__ out) {
  __shared__ unsigned int       sh[2 * BINS];   // 16 KB hist
  __shared__ unsigned long long swarp[NW];
  __shared__ float              sred[NW];
  __shared__ int                s0[NW], s1[NW];
  __shared__ int                sflag, slast;

  const int n    = blockIdx.y;
  const int b    = blockIdx.x;
  const int tid  = threadIdx.x;
  const int lane = tid & 31;
  const int w    = tid >> 5;

  for (int i = tid; i < 2 * BINS; i += HT) sh[i] = 0u;

  // Detect targets dtype: if int32, odd 32-bit words carry real data -> some
  // nonzero. If int64 (values 0/1), odd words are all zero. Doubles as barrier.
  const int* t32 = (const int*)tgt;
  int probe = t32[2 * tid + 1];
  bool is32 = __syncthreads_or(probe != 0);

  // ---------------- histogram phase ----------------
  const int base = b * PXB;
  const float* __restrict__ x0 = x + ((size_t)n * NC + 0) * PP;
  const float* __restrict__ x1 = x + ((size_t)n * NC + 1) * PP;
  int c0 = 0, c1 = 0;
#pragma unroll 4
  for (int it = 0; it < ITERS; it++) {
    const int p = base + (it * HT + tid) * 4;

    // pack target quad into 4 mask bits immediately (keeps regs low)
    unsigned int mbits;
    if (is32) {
      int4 q = *(const int4*)(t32 + (size_t)n * PP + p);
      mbits = (unsigned)(q.x == 0) | ((unsigned)(q.y == 0) << 1) |
              ((unsigned)(q.z == 0) << 2) | ((unsigned)(q.w == 0) << 3);
    } else {
      longlong4 q = *(const longlong4*)((const long long*)tgt + (size_t)n * PP + p);
      mbits = (unsigned)(q.x == 0) | ((unsigned)(q.y == 0) << 1) |
              ((unsigned)(q.z == 0) << 2) | ((unsigned)(q.w == 0) << 3);
    }
    float4 v0 = *(const float4*)(x0 + p);
    float4 v1 = *(const float4*)(x1 + p);
    float xs0[4] = {v0.x, v0.y, v0.z, v0.w};
    float xs1[4] = {v1.x, v1.y, v1.z, v1.w};

#pragma unroll
    for (int k = 0; k < 4; k++) {
      bool  m0 = (mbits >> k) & 1u;       // class-0 mask; class-1 mask = !m0
      float a0 = xs0[k], a1 = xs1[k];
      c0 += (a0 > 0.25f);
      c1 += (a1 > 0.25f);
      float d0 = m0 ? (1.0f - a0) : a0;   // |mask - x|
      float d1 = m0 ? a1 : (1.0f - a1);
      unsigned int b0 = min((unsigned int)(d0 * (float)BINS), (unsigned int)(BINS - 1));
      unsigned int b1 = min((unsigned int)(d1 * (float)BINS), (unsigned int)(BINS - 1));
      atomicAdd(&sh[b0],        m0 ? 0x10000u : 1u);
      atomicAdd(&sh[BINS + b1], m0 ? 1u : 0x10000u);
    }
  }
  __syncthreads();

  // flush: plain vectorized stores to this block's private slot
  uint4* __restrict__ dst =
      (uint4*)(g_part + ((size_t)(n * BPS + b) * NC) * BINS);
  const uint4* __restrict__ src = (const uint4*)sh;
#pragma unroll
  for (int i = tid; i < (2 * BINS) / 4; i += HT) dst[i] = src[i];

  // npred block reduce + 2 global atomics
#pragma unroll
  for (int off = 16; off; off >>= 1) {
    c0 += __shfl_down_sync(0xffffffffu, c0, off);
    c1 += __shfl_down_sync(0xffffffffu, c1, off);
  }
  if (lane == 0) { s0[w] = c0; s1[w] = c1; }
  __syncthreads();
  if (tid == 0) {
    int a = 0, bb = 0;
#pragma unroll
    for (int i = 0; i < NW; i++) { a += s0[i]; bb += s1[i]; }
    atomicAdd(&g_npred[n], a);
    atomicAdd(&g_npred[NB + n], bb);
  }

  // ---------------- arrival: last block of this sample runs the scan tail ----
  __threadfence();              // flush stores + npred atomics globally visible
  __syncthreads();
  if (tid == 0) {
    int old = atomicAdd(&g_cnt[n], 1);
    sflag = (old == BPS - 1);
  }
  __syncthreads();
  if (!sflag) return;
  __threadfence();              // acquire

  // ---------------- scan tail: both class rows of sample n ----------------
  for (int cc = 0; cc < NC; cc++) {
    const int r = cc * NB + n;
    // thread owns SEG=2 bins [g, g+1]; thread 0 owns the HIGHEST bins
    const int g = BINS - SEG - tid * SEG;

    unsigned int h1[SEG], htot[SEG];
#pragma unroll
    for (int j = 0; j < SEG; j++) { h1[j] = 0u; htot[j] = 0u; }

#pragma unroll
    for (int bb = 0; bb < BPS; bb++) {
      uint2 v = __ldcg((const uint2*)(g_part +
                 ((size_t)(n * BPS + bb) * NC + cc) * BINS + g));
      unsigned int vv[2] = {v.x, v.y};
#pragma unroll
      for (int j = 0; j < SEG; j++) {
        unsigned int one = vv[j] >> 16;
        h1[j]   += one;
        htot[j] += one + (vv[j] & 0xffffu);
      }
    }

    unsigned int ss1 = 0, sst = 0;
#pragma unroll
    for (int j = 0; j < SEG; j++) { ss1 += h1[j]; sst += htot[j]; }

    // inclusive block scan over packed (s1|st)
    unsigned long long mine = ((unsigned long long)ss1 << 32) | (unsigned long long)sst;
    unsigned long long inc = mine;
#pragma unroll
    for (int off = 1; off < 32; off <<= 1) {
      unsigned long long u = __shfl_up_sync(0xffffffffu, inc, off);
      if (lane >= off) inc += u;
    }
    if (lane == 31) swarp[w] = inc;
    __syncthreads();
    if (w == 0) {
      unsigned long long v = (lane < NW) ? swarp[lane] : 0ull;
#pragma unroll
      for (int off = 1; off < NW; off <<= 1) {
        unsigned long long u = __shfl_up_sync(0xffffffffu, v, off);
        if (lane >= off) v += u;
      }
      if (lane < NW) swarp[lane] = v;
    }
    __syncthreads();
    unsigned long long woff = (w == 0) ? 0ull : swarp[w - 1];
    unsigned long long tot  = swarp[NW - 1];
    unsigned long long excl = woff + inc - mine;

    const unsigned int gts = (unsigned int)(tot >> 32);
    unsigned int K1 = (unsigned int)(excl >> 32);
    unsigned int K  = (unsigned int)(excl & 0xffffffffull);

    float iou_prev = (K == 0)
        ? 0.0f
        : 1.0f - __fdividef((float)(gts - K1), (float)(gts + K - K1));

    float acc = 0.0f;
#pragma unroll
    for (int j = SEG - 1; j >= 0; j--) {
      if (htot[j]) {
        K1 += h1[j];
        K  += htot[j];
        float iou = 1.0f - __fdividef((float)(gts - K1), (float)(gts + K - K1));
        float d   = ((float)(g + j) + 0.5f) * (1.0f / (float)BINS);
        acc += d * (iou - iou_prev);
        iou_prev = iou;
      }
    }

    // block reduce acc (fixed tree -> deterministic)
#pragma unroll
    for (int off = 16; off; off >>= 1)
      acc += __shfl_down_sync(0xffffffffu, acc, off);
    if (lane == 0) sred[w] = acc;
    __syncthreads();
    if (tid == 0) {
      float per = 0.0f;
#pragma unroll
      for (int i = 0; i < NW; i++) per += sred[i];
      int   np    = __ldcg(&g_npred[r]);
      float cwv   = cw[cc];
      bool  empty = (gts == 0) && (np == 0);
      bool  valid = (cwv != 0.0f) && !empty;
      g_wrow[r]  = valid ? per * tw[n] * cwv : 0.0f;
      g_valid[r] = valid ? 1u : 0u;
      g_npred[r] = 0;                  // reset for next replay
    }
    __syncthreads();
  }

  // ---------------- completion: last sample-finisher does the final sum ----
  if (tid == 0) {
    g_cnt[n] = 0;                      // reset for next replay
    __threadfence();
    int old = atomicAdd(&g_done, 1);
    slast = (old == NB - 1);
  }
  __syncthreads();
  if (!slast) return;
  __threadfence();

  // parallel deterministic final reduction (64 lanes of warps 0-1)
  {
    float Wv = 0.0f, Vv = 0.0f;
    if (tid < ROWS) {
      Wv = __ldcg(&g_wrow[tid]);
      Vv = (float)__ldcg(&g_valid[tid]);
    }
    if (tid < 64) {
#pragma unroll
      for (int off = 16; off; off >>= 1) {
        Wv += __shfl_down_sync(0xffffffffu, Wv, off);
        Vv += __shfl_down_sync(0xffffffffu, Vv, off);
      }
      if (lane == 0) { sred[w] = Wv; ((float*)swarp)[w] = Vv; }
    }
    __syncthreads();
    if (tid == 0) {
      float W = sred[0] + sred[1];
      float V = ((float*)swarp)[0] + ((float*)swarp)[1];
      out[0] = W / (float)NB / V;
      g_done = 0;                      // reset for next replay
    }
  }
}

// ---------------------------------------------------------------- launch
extern "C" void kernel_launch(void* const* d_in, const int* in_sizes, int n_in,
                              void* d_out, int out_size) {
  const float* x   = (const float*)d_in[0];
  const void*  tgt = d_in[1];
  const float* cw  = (const float*)d_in[2];
  const float* tw  = (const float*)d_in[3];
  float* out = (float*)d_out;

  dim3 grid(BPS, NB);
  k_all<<<grid, HT>>>(x, tgt, cw, tw, out);
}